// round 4
// baseline (speedup 1.0000x reference)
#include <cuda_runtime.h>
#include <math.h>

#define BB    8
#define NN1   4096
#define NN2   4096
#define TILE  2048          // pc2 points staged per smem tile (32KB of float4)

// Scratch (device globals — no runtime allocation allowed)
__device__ float g_near[BB * 3 * NN1];
__device__ float g_dist[BB * NN1];

// ---------------------------------------------------------------------------
// Kernel 1: soft nearest neighbor.
// One thread = one query point. pc2 (x,y,z) staged tile-by-tile in 32KB of
// shared memory as float4 (stays under the 48KB default dynamic-smem limit,
// so no cudaFuncSetAttribute is needed). Online softmax over scores
// s = 2 / max(d, 1e-5): maintain running smax; any term with s < smax - 88
// underflows to exactly 0 in fp32 (identical to the reference softmax),
// which translates to d >= dthr with dthr = 2/(smax-88).
// Common path per pair: 1 LDS.128 + 3 FADD + 3 FMA + 1 FSETP + branch.
// ---------------------------------------------------------------------------
__global__ void __launch_bounds__(256) nn_soft_kernel(const float* __restrict__ pc1,
                                                      const float* __restrict__ pc2)
{
    extern __shared__ float4 sh[];   // TILE entries = 32KB
    const int b = blockIdx.y;
    const float* p2 = pc2 + (size_t)b * 4 * NN2;

    const int n = blockIdx.x * 256 + threadIdx.x;
    const float* p1 = pc1 + (size_t)b * 4 * NN1;
    const float qx = p1[n], qy = p1[NN1 + n], qz = p1[2 * NN1 + n];

    const float INF = __int_as_float(0x7f800000);
    float smax = -INF;
    float dthr = INF;
    float sumw = 0.0f, a0 = 0.0f, a1 = 0.0f, a2 = 0.0f;

    for (int t0 = 0; t0 < NN2; t0 += TILE) {
        __syncthreads();
        for (int m = threadIdx.x; m < TILE; m += 256) {
            int g = t0 + m;
            sh[m] = make_float4(p2[g], p2[NN2 + g], p2[2 * NN2 + g], 0.0f);
        }
        __syncthreads();

        #pragma unroll 4
        for (int m = 0; m < TILE; ++m) {
            float4 p = sh[m];
            float dx = qx - p.x, dy = qy - p.y, dz = qz - p.z;
            float d = fmaf(dx, dx, fmaf(dy, dy, dz * dz));
            if (d < dthr) {
                float s = __fdividef(2.0f, fmaxf(d, 1e-5f));
                if (s > smax) {
                    // rescale existing accumulators to the new max
                    float corr = __expf(smax - s);   // __expf(-inf) = 0 on first hit
                    sumw *= corr; a0 *= corr; a1 *= corr; a2 *= corr;
                    smax = s;
                    dthr = (s > 88.0f) ? __fdividef(2.0f, s - 88.0f) : INF;
                }
                float w = __expf(s - smax);
                sumw += w;
                a0 = fmaf(w, p.x, a0);
                a1 = fmaf(w, p.y, a1);
                a2 = fmaf(w, p.z, a2);
            }
        }
    }

    float inv = __fdividef(1.0f, sumw);          // sumw >= 1 always
    float nx = a0 * inv, ny = a1 * inv, nz = a2 * inv;
    float dx = qx - nx, dy = qy - ny, dz = qz - nz;
    // channel 3: pc1[3]=1 and sum(softmax)=1; its contribution to dist is
    // ~(few ulp)^2, relative ~1e-12 -> omitted
    float dist = sqrtf(dx * dx + dy * dy + dz * dz);

    g_near[((size_t)b * 3 + 0) * NN1 + n] = nx;
    g_near[((size_t)b * 3 + 1) * NN1 + n] = ny;
    g_near[((size_t)b * 3 + 2) * NN1 + n] = nz;
    g_dist[(size_t)b * NN1 + n] = dist;
}

// ---------------------------------------------------------------------------
// Kernel 2: one block per batch. Mean distance, inlier mask (step sigmoid),
// centroids and cross-covariance H in fp64, then thread 0 does a 3x3 SVD
// (Jacobi on H^T H), Kabsch sign fix, R/t/T/quaternion, writes outputs.
// Output layout: T[8*16] | q[8*4] | t[8*3]  (concatenated flattened arrays)
// ---------------------------------------------------------------------------
__device__ inline double det3(const double A[3][3])
{
    return A[0][0] * (A[1][1] * A[2][2] - A[1][2] * A[2][1])
         - A[0][1] * (A[1][0] * A[2][2] - A[1][2] * A[2][0])
         + A[0][2] * (A[1][0] * A[2][1] - A[1][1] * A[2][0]);
}

__global__ void __launch_bounds__(256) finalize_kernel(const float* __restrict__ pc1,
                                                       float* __restrict__ out)
{
    const int b = blockIdx.x;
    const int tid = threadIdx.x;
    const float* p1 = pc1 + (size_t)b * 4 * NN1;
    const float* nr = g_near + (size_t)b * 3 * NN1;
    const float* ds = g_dist + (size_t)b * NN1;

    __shared__ double warp_red[16][8];
    __shared__ double s_mean;

    // ---- phase 1: mean distance ----
    double lsum = 0.0;
    for (int i = tid; i < NN1; i += 256) lsum += (double)ds[i];
    for (int o = 16; o > 0; o >>= 1) lsum += __shfl_down_sync(0xffffffffu, lsum, o);
    if ((tid & 31) == 0) warp_red[0][tid >> 5] = lsum;
    __syncthreads();
    if (tid == 0) {
        double t = 0.0;
        for (int w = 0; w < 8; ++w) t += warp_red[0][w];
        s_mean = t / (double)NN1;
    }
    __syncthreads();
    const float mean = (float)s_mean;

    // ---- phase 2: masked sums ----
    double acc[16];
    #pragma unroll
    for (int k = 0; k < 16; ++k) acc[k] = 0.0;

    for (int i = tid; i < NN1; i += 256) {
        float d = ds[i];
        float z = (d - mean - 1e-5f) * -1e10f;     // REJECT_RATIO=1
        float ind = 1.0f / (1.0f + __expf(-z));    // exact 0/1 step in fp32
        if (ind > 0.0f) {
            double w = (double)ind;
            double x1 = p1[i], y1 = p1[NN1 + i], z1 = p1[2 * NN1 + i];
            double x2 = nr[i], y2 = nr[NN1 + i], z2 = nr[2 * NN1 + i];
            acc[0] += w;
            acc[1] += w * x1;  acc[2] += w * y1;  acc[3] += w * z1;
            acc[4] += w * x2;  acc[5] += w * y2;  acc[6] += w * z2;
            acc[7]  += w * x1 * x2;  acc[8]  += w * x1 * y2;  acc[9]  += w * x1 * z2;
            acc[10] += w * y1 * x2;  acc[11] += w * y1 * y2;  acc[12] += w * y1 * z2;
            acc[13] += w * z1 * x2;  acc[14] += w * z1 * y2;  acc[15] += w * z1 * z2;
        }
    }
    #pragma unroll
    for (int k = 0; k < 16; ++k) {
        double v = acc[k];
        for (int o = 16; o > 0; o >>= 1) v += __shfl_down_sync(0xffffffffu, v, o);
        if ((tid & 31) == 0) warp_red[k][tid >> 5] = v;
    }
    __syncthreads();
    if (tid != 0) return;

    double tot[16];
    for (int k = 0; k < 16; ++k) {
        double t = 0.0;
        for (int w = 0; w < 8; ++w) t += warp_red[k][w];
        tot[k] = t;
    }

    const double wsum = tot[0];
    double c1[3] = { tot[1] / wsum, tot[2] / wsum, tot[3] / wsum };
    double c2[3] = { tot[4] / wsum, tot[5] / wsum, tot[6] / wsum };
    double H[3][3];
    for (int i = 0; i < 3; ++i)
        for (int j = 0; j < 3; ++j)
            H[i][j] = tot[7 + i * 3 + j] - tot[1 + i] * tot[4 + j] / wsum;

    // ---- SVD of H via Jacobi on S = H^T H ----
    double S[3][3], V[3][3];
    for (int i = 0; i < 3; ++i)
        for (int j = 0; j < 3; ++j) {
            double t = 0.0;
            for (int k = 0; k < 3; ++k) t += H[k][i] * H[k][j];
            S[i][j] = t;
            V[i][j] = (i == j) ? 1.0 : 0.0;
        }
    for (int sweep = 0; sweep < 6; ++sweep) {
        for (int pi = 0; pi < 3; ++pi) {
            const int p = (pi == 2) ? 1 : 0;
            const int q = (pi == 0) ? 1 : 2;
            double apq = S[p][q];
            if (fabs(apq) < 1e-300) continue;
            double theta = (S[q][q] - S[p][p]) / (2.0 * apq);
            double tt = copysign(1.0, theta) / (fabs(theta) + sqrt(theta * theta + 1.0));
            double c = 1.0 / sqrt(tt * tt + 1.0);
            double sn = tt * c;
            for (int k = 0; k < 3; ++k) { double a = S[k][p], bb = S[k][q]; S[k][p] = c * a - sn * bb; S[k][q] = sn * a + c * bb; }
            for (int k = 0; k < 3; ++k) { double a = S[p][k], bb = S[q][k]; S[p][k] = c * a - sn * bb; S[q][k] = sn * a + c * bb; }
            for (int k = 0; k < 3; ++k) { double a = V[k][p], bb = V[k][q]; V[k][p] = c * a - sn * bb; V[k][q] = sn * a + c * bb; }
        }
    }
    double lam[3] = { S[0][0], S[1][1], S[2][2] };
    for (int i = 0; i < 2; ++i)
        for (int j = i + 1; j < 3; ++j)
            if (lam[j] > lam[i]) {
                double t = lam[i]; lam[i] = lam[j]; lam[j] = t;
                for (int k = 0; k < 3; ++k) { double v = V[k][i]; V[k][i] = V[k][j]; V[k][j] = v; }
            }

    // U columns: u_i = H v_i / sigma_i, with Gram-Schmidt polish (keeps det sign)
    double U[3][3];
    for (int i = 0; i < 3; ++i) {
        double u[3];
        for (int k = 0; k < 3; ++k) {
            double t = 0.0;
            for (int j = 0; j < 3; ++j) t += H[k][j] * V[j][i];
            u[k] = t;
        }
        for (int pc = 0; pc < i; ++pc) {
            double dp = u[0] * U[0][pc] + u[1] * U[1][pc] + u[2] * U[2][pc];
            for (int k = 0; k < 3; ++k) u[k] -= dp * U[k][pc];
        }
        double nrm = sqrt(u[0] * u[0] + u[1] * u[1] + u[2] * u[2]);
        double innr = 1.0 / fmax(nrm, 1e-300);
        for (int k = 0; k < 3; ++k) U[k][i] = u[k] * innr;
    }

    double sign = (det3(U) * det3(V) < 0.0) ? -1.0 : 1.0;
    for (int k = 0; k < 3; ++k) V[k][2] *= sign;

    double R[3][3];
    for (int i = 0; i < 3; ++i)
        for (int j = 0; j < 3; ++j) {
            double t = 0.0;
            for (int k = 0; k < 3; ++k) t += V[i][k] * U[j][k];
            R[i][j] = t;
        }
    double tv[3];
    for (int i = 0; i < 3; ++i)
        tv[i] = c2[i] - (R[i][0] * c1[0] + R[i][1] * c1[1] + R[i][2] * c1[2]);

    // ---- write outputs: T | q | t ----
    float* To = out + b * 16;
    for (int i = 0; i < 3; ++i) {
        for (int j = 0; j < 3; ++j) To[i * 4 + j] = (float)R[i][j];
        To[i * 4 + 3] = (float)tv[i];
    }
    To[12] = 0.0f; To[13] = 0.0f; To[14] = 0.0f; To[15] = 1.0f;

    double trp = R[0][0] + R[1][1] + R[2][2];
    double qw = 0.5 * sqrt(fmax(1.0 + trp, 1e-12));
    double qx = 0.5 * sqrt(fmax(1.0 + R[0][0] - R[1][1] - R[2][2], 1e-12))
              * ((R[2][1] - R[1][2] >= 0.0) ? 1.0 : -1.0);
    double qy = 0.5 * sqrt(fmax(1.0 - R[0][0] + R[1][1] - R[2][2], 1e-12))
              * ((R[0][2] - R[2][0] >= 0.0) ? 1.0 : -1.0);
    double qz = 0.5 * sqrt(fmax(1.0 - R[0][0] - R[1][1] + R[2][2], 1e-12))
              * ((R[1][0] - R[0][1] >= 0.0) ? 1.0 : -1.0);

    float* qo = out + BB * 16 + b * 4;
    qo[0] = (float)qw; qo[1] = (float)qx; qo[2] = (float)qy; qo[3] = (float)qz;

    float* to = out + BB * 16 + BB * 4 + b * 3;
    to[0] = (float)tv[0]; to[1] = (float)tv[1]; to[2] = (float)tv[2];
}

// ---------------------------------------------------------------------------
extern "C" void kernel_launch(void* const* d_in, const int* in_sizes, int n_in,
                              void* d_out, int out_size)
{
    const float* pc1 = (const float*)d_in[0];
    const float* pc2 = (const float*)d_in[1];
    float* out = (float*)d_out;

    dim3 grid(NN1 / 256, BB);
    nn_soft_kernel<<<grid, 256, TILE * 16>>>(pc1, pc2);
    finalize_kernel<<<BB, 256>>>(pc1, out);
}

// round 10
// speedup vs baseline: 2.0306x; 2.0306x over previous
#include <cuda_runtime.h>
#include <math.h>

#define BB    8
#define NN1   4096
#define NN2   4096
#define TILE  2048          // pc2 points staged per smem tile (32KB static)
#define CUT   30.0f         // exp(s-smax) < e^-30 -> contribution < 1e-13, dropped

// Scratch (device globals — no runtime allocation allowed)
__device__ float g_near[BB * 3 * NN1];
__device__ float g_dist[BB * NN1];

// ---------------------------------------------------------------------------
// Kernel 1: soft nearest neighbor, two-pass.
// Pass 1 (branchless): dminp = min over d' = |p2|^2 - 2 q.p2  (q^2 folded out).
// Then smax = 2/max(dmin,1e-5), threshold dthr' = 2/(smax-CUT) - q2, CLAMPED
// to be >= dminp (the argmin must always pass: pass-2 d' values are bitwise
// identical to pass-1, so  dp <= dthr'  includes the argmin and sumw >= 1,
// eliminating the 0*inf NaN that killed the unclamped version).
// Pass 2: groups of 8 elements, one group-min + ONE branch per group
// (amortizes the BSSY/BSYNC divergence envelope); the rare heavy path
// accumulates softmax terms with fixed smax (no online rescale needed).
// ---------------------------------------------------------------------------
__global__ void __launch_bounds__(128) nn_soft_kernel(const float* __restrict__ pc1,
                                                      const float* __restrict__ pc2)
{
    __shared__ float4 sh[TILE];   // 32KB
    const int b = blockIdx.y;
    const float* p2 = pc2 + (size_t)b * 4 * NN2;

    const int n = blockIdx.x * 128 + threadIdx.x;
    const float* p1 = pc1 + (size_t)b * 4 * NN1;
    const float qx = p1[n], qy = p1[NN1 + n], qz = p1[2 * NN1 + n];
    const float q2 = qx * qx + qy * qy + qz * qz;

    const float INF = __int_as_float(0x7f800000);

    // ---------------- pass 1: min over d' ----------------
    float dminp = INF;
    for (int t0 = 0; t0 < NN2; t0 += TILE) {
        __syncthreads();
        for (int m = threadIdx.x; m < TILE; m += 128) {
            int g = t0 + m;
            float x = p2[g], y = p2[NN2 + g], z = p2[2 * NN2 + g];
            sh[m] = make_float4(x, y, z, x * x + y * y + z * z);
        }
        __syncthreads();

        #pragma unroll 8
        for (int m = 0; m < TILE; ++m) {
            float4 p = sh[m];
            float dot = fmaf(qx, p.x, fmaf(qy, p.y, qz * p.z));
            float dp  = fmaf(-2.0f, dot, p.w);
            dminp = fminf(dminp, dp);
        }
    }

    const float dmin = dminp + q2;                       // true min distance^2
    const float smax = __fdividef(2.0f, fmaxf(dmin, 1e-5f));
    // threshold on d' (q2 folded): d < dthr  <=>  d' < dthr - q2.
    // CLAMP to dminp so the argmin always passes (NaN guard, see header).
    const float dthr_p = (smax > CUT)
                       ? fmaxf(__fdividef(2.0f, smax - CUT) - q2, dminp)
                       : INF;

    // ---------------- pass 2: accumulate softmax ----------------
    float sumw = 0.0f, a0 = 0.0f, a1 = 0.0f, a2 = 0.0f;

    for (int t0 = 0; t0 < NN2; t0 += TILE) {
        __syncthreads();
        for (int m = threadIdx.x; m < TILE; m += 128) {
            int g = t0 + m;
            float x = p2[g], y = p2[NN2 + g], z = p2[2 * NN2 + g];
            sh[m] = make_float4(x, y, z, x * x + y * y + z * z);
        }
        __syncthreads();

        for (int m0 = 0; m0 < TILE; m0 += 8) {
            float dp[8];
            float gmin = INF;
            #pragma unroll
            for (int j = 0; j < 8; ++j) {
                float4 p = sh[m0 + j];
                float dot = fmaf(qx, p.x, fmaf(qy, p.y, qz * p.z));
                dp[j] = fmaf(-2.0f, dot, p.w);
                gmin = fminf(gmin, dp[j]);
            }
            if (gmin <= dthr_p) {                 // rare for sparse queries
                #pragma unroll
                for (int j = 0; j < 8; ++j) {
                    if (dp[j] <= dthr_p) {
                        float d = fmaxf(dp[j] + q2, 1e-5f);
                        float s = __fdividef(2.0f, d);
                        float w = __expf(s - smax);   // <= 1 by construction
                        float4 p = sh[m0 + j];
                        sumw += w;
                        a0 = fmaf(w, p.x, a0);
                        a1 = fmaf(w, p.y, a1);
                        a2 = fmaf(w, p.z, a2);
                    }
                }
            }
        }
    }

    float inv = __fdividef(1.0f, sumw);          // sumw >= 1 (argmin included)
    float nx = a0 * inv, ny = a1 * inv, nz = a2 * inv;
    float ddx = qx - nx, ddy = qy - ny, ddz = qz - nz;
    // channel 3: pc1[3]=1 and sum(softmax)=1; contribution ~ulp^2 -> omitted
    float dist = sqrtf(ddx * ddx + ddy * ddy + ddz * ddz);

    g_near[((size_t)b * 3 + 0) * NN1 + n] = nx;
    g_near[((size_t)b * 3 + 1) * NN1 + n] = ny;
    g_near[((size_t)b * 3 + 2) * NN1 + n] = nz;
    g_dist[(size_t)b * NN1 + n] = dist;
}

// ---------------------------------------------------------------------------
// Kernel 2: one block per batch. Mean distance, inlier mask (step sigmoid),
// centroids and cross-covariance H in fp64, then thread 0 does a 3x3 SVD
// (Jacobi on H^T H), Kabsch sign fix, R/t/T/quaternion, writes outputs.
// Output layout: T[8*16] | q[8*4] | t[8*3]   (identical to the R4 passing ver)
// ---------------------------------------------------------------------------
__device__ inline double det3(const double A[3][3])
{
    return A[0][0] * (A[1][1] * A[2][2] - A[1][2] * A[2][1])
         - A[0][1] * (A[1][0] * A[2][2] - A[1][2] * A[2][0])
         + A[0][2] * (A[1][0] * A[2][1] - A[1][1] * A[2][0]);
}

__global__ void __launch_bounds__(256) finalize_kernel(const float* __restrict__ pc1,
                                                       float* __restrict__ out)
{
    const int b = blockIdx.x;
    const int tid = threadIdx.x;
    const float* p1 = pc1 + (size_t)b * 4 * NN1;
    const float* nr = g_near + (size_t)b * 3 * NN1;
    const float* ds = g_dist + (size_t)b * NN1;

    __shared__ double warp_red[16][8];
    __shared__ double s_mean;

    // ---- phase 1: mean distance ----
    double lsum = 0.0;
    for (int i = tid; i < NN1; i += 256) lsum += (double)ds[i];
    for (int o = 16; o > 0; o >>= 1) lsum += __shfl_down_sync(0xffffffffu, lsum, o);
    if ((tid & 31) == 0) warp_red[0][tid >> 5] = lsum;
    __syncthreads();
    if (tid == 0) {
        double t = 0.0;
        for (int w = 0; w < 8; ++w) t += warp_red[0][w];
        s_mean = t / (double)NN1;
    }
    __syncthreads();
    const float mean = (float)s_mean;

    // ---- phase 2: masked sums ----
    double acc[16];
    #pragma unroll
    for (int k = 0; k < 16; ++k) acc[k] = 0.0;

    for (int i = tid; i < NN1; i += 256) {
        float d = ds[i];
        float z = (d - mean - 1e-5f) * -1e10f;     // REJECT_RATIO=1
        float ind = 1.0f / (1.0f + __expf(-z));    // exact 0/1 step in fp32
        if (ind > 0.0f) {
            double w = (double)ind;
            double x1 = p1[i], y1 = p1[NN1 + i], z1 = p1[2 * NN1 + i];
            double x2 = nr[i], y2 = nr[NN1 + i], z2 = nr[2 * NN1 + i];
            acc[0] += w;
            acc[1] += w * x1;  acc[2] += w * y1;  acc[3] += w * z1;
            acc[4] += w * x2;  acc[5] += w * y2;  acc[6] += w * z2;
            acc[7]  += w * x1 * x2;  acc[8]  += w * x1 * y2;  acc[9]  += w * x1 * z2;
            acc[10] += w * y1 * x2;  acc[11] += w * y1 * y2;  acc[12] += w * y1 * z2;
            acc[13] += w * z1 * x2;  acc[14] += w * z1 * y2;  acc[15] += w * z1 * z2;
        }
    }
    #pragma unroll
    for (int k = 0; k < 16; ++k) {
        double v = acc[k];
        for (int o = 16; o > 0; o >>= 1) v += __shfl_down_sync(0xffffffffu, v, o);
        if ((tid & 31) == 0) warp_red[k][tid >> 5] = v;
    }
    __syncthreads();
    if (tid != 0) return;

    double tot[16];
    for (int k = 0; k < 16; ++k) {
        double t = 0.0;
        for (int w = 0; w < 8; ++w) t += warp_red[k][w];
        tot[k] = t;
    }

    const double wsum = tot[0];
    double c1[3] = { tot[1] / wsum, tot[2] / wsum, tot[3] / wsum };
    double c2[3] = { tot[4] / wsum, tot[5] / wsum, tot[6] / wsum };
    double H[3][3];
    for (int i = 0; i < 3; ++i)
        for (int j = 0; j < 3; ++j)
            H[i][j] = tot[7 + i * 3 + j] - tot[1 + i] * tot[4 + j] / wsum;

    // ---- SVD of H via Jacobi on S = H^T H ----
    double S[3][3], V[3][3];
    for (int i = 0; i < 3; ++i)
        for (int j = 0; j < 3; ++j) {
            double t = 0.0;
            for (int k = 0; k < 3; ++k) t += H[k][i] * H[k][j];
            S[i][j] = t;
            V[i][j] = (i == j) ? 1.0 : 0.0;
        }
    for (int sweep = 0; sweep < 6; ++sweep) {
        for (int pi = 0; pi < 3; ++pi) {
            const int p = (pi == 2) ? 1 : 0;
            const int q = (pi == 0) ? 1 : 2;
            double apq = S[p][q];
            if (fabs(apq) < 1e-300) continue;
            double theta = (S[q][q] - S[p][p]) / (2.0 * apq);
            double tt = copysign(1.0, theta) / (fabs(theta) + sqrt(theta * theta + 1.0));
            double c = 1.0 / sqrt(tt * tt + 1.0);
            double sn = tt * c;
            for (int k = 0; k < 3; ++k) { double a = S[k][p], bb = S[k][q]; S[k][p] = c * a - sn * bb; S[k][q] = sn * a + c * bb; }
            for (int k = 0; k < 3; ++k) { double a = S[p][k], bb = S[q][k]; S[p][k] = c * a - sn * bb; S[q][k] = sn * a + c * bb; }
            for (int k = 0; k < 3; ++k) { double a = V[k][p], bb = V[k][q]; V[k][p] = c * a - sn * bb; V[k][q] = sn * a + c * bb; }
        }
    }
    double lam[3] = { S[0][0], S[1][1], S[2][2] };
    for (int i = 0; i < 2; ++i)
        for (int j = i + 1; j < 3; ++j)
            if (lam[j] > lam[i]) {
                double t = lam[i]; lam[i] = lam[j]; lam[j] = t;
                for (int k = 0; k < 3; ++k) { double v = V[k][i]; V[k][i] = V[k][j]; V[k][j] = v; }
            }

    // U columns: u_i = H v_i / sigma_i, with Gram-Schmidt polish (keeps det sign)
    double U[3][3];
    for (int i = 0; i < 3; ++i) {
        double u[3];
        for (int k = 0; k < 3; ++k) {
            double t = 0.0;
            for (int j = 0; j < 3; ++j) t += H[k][j] * V[j][i];
            u[k] = t;
        }
        for (int pc = 0; pc < i; ++pc) {
            double dpp = u[0] * U[0][pc] + u[1] * U[1][pc] + u[2] * U[2][pc];
            for (int k = 0; k < 3; ++k) u[k] -= dpp * U[k][pc];
        }
        double nrm = sqrt(u[0] * u[0] + u[1] * u[1] + u[2] * u[2]);
        double innr = 1.0 / fmax(nrm, 1e-300);
        for (int k = 0; k < 3; ++k) U[k][i] = u[k] * innr;
    }

    double sign = (det3(U) * det3(V) < 0.0) ? -1.0 : 1.0;
    for (int k = 0; k < 3; ++k) V[k][2] *= sign;

    double R[3][3];
    for (int i = 0; i < 3; ++i)
        for (int j = 0; j < 3; ++j) {
            double t = 0.0;
            for (int k = 0; k < 3; ++k) t += V[i][k] * U[j][k];
            R[i][j] = t;
        }
    double tv[3];
    for (int i = 0; i < 3; ++i)
        tv[i] = c2[i] - (R[i][0] * c1[0] + R[i][1] * c1[1] + R[i][2] * c1[2]);

    // ---- write outputs: T | q | t ----
    float* To = out + b * 16;
    for (int i = 0; i < 3; ++i) {
        for (int j = 0; j < 3; ++j) To[i * 4 + j] = (float)R[i][j];
        To[i * 4 + 3] = (float)tv[i];
    }
    To[12] = 0.0f; To[13] = 0.0f; To[14] = 0.0f; To[15] = 1.0f;

    double trp = R[0][0] + R[1][1] + R[2][2];
    double qw = 0.5 * sqrt(fmax(1.0 + trp, 1e-12));
    double qx = 0.5 * sqrt(fmax(1.0 + R[0][0] - R[1][1] - R[2][2], 1e-12))
              * ((R[2][1] - R[1][2] >= 0.0) ? 1.0 : -1.0);
    double qy = 0.5 * sqrt(fmax(1.0 - R[0][0] + R[1][1] - R[2][2], 1e-12))
              * ((R[0][2] - R[2][0] >= 0.0) ? 1.0 : -1.0);
    double qz = 0.5 * sqrt(fmax(1.0 - R[0][0] - R[1][1] + R[2][2], 1e-12))
              * ((R[1][0] - R[0][1] >= 0.0) ? 1.0 : -1.0);

    float* qo = out + BB * 16 + b * 4;
    qo[0] = (float)qw; qo[1] = (float)qx; qo[2] = (float)qy; qo[3] = (float)qz;

    float* to = out + BB * 16 + BB * 4 + b * 3;
    to[0] = (float)tv[0]; to[1] = (float)tv[1]; to[2] = (float)tv[2];
}

// ---------------------------------------------------------------------------
extern "C" void kernel_launch(void* const* d_in, const int* in_sizes, int n_in,
                              void* d_out, int out_size)
{
    const float* pc1 = (const float*)d_in[0];
    const float* pc2 = (const float*)d_in[1];
    float* out = (float*)d_out;

    dim3 grid(NN1 / 128, BB);
    nn_soft_kernel<<<grid, 128>>>(pc1, pc2);
    finalize_kernel<<<BB, 256>>>(pc1, out);
}

// round 12
// speedup vs baseline: 4.3044x; 2.1198x over previous
#include <cuda_runtime.h>
#include <math.h>

#define BB      8
#define NN1     4096
#define NN2     4096
#define NSLICE  4
#define SLICE   (NN2 / NSLICE)      // 1024 pc2 points per slice (16KB float4)
#define CUT     30.0f               // exp(s-smax) < e^-30 -> negligible, dropped

// Scratch (device globals — no runtime allocation allowed)
__device__ float g_partmin[NSLICE * BB * NN1];          // per-slice min of d'
__device__ float g_part[NSLICE * 4 * BB * NN1];         // per-slice {sumw,a0,a1,a2}
__device__ float g_near[BB * 3 * NN1];
__device__ float g_dist[BB * NN1];

// ---------------------------------------------------------------------------
// Kernel A: branchless per-slice min of d' = |p2|^2 - 2 q.p2  (q^2 folded out)
// grid = (NN1/128, NSLICE, BB), 128 threads. 16KB smem -> ~7 CTAs/SM.
// ---------------------------------------------------------------------------
__global__ void __launch_bounds__(128) nn_min_kernel(const float* __restrict__ pc1,
                                                     const float* __restrict__ pc2)
{
    __shared__ float4 sh[SLICE];
    const int b = blockIdx.z;
    const int s = blockIdx.y;
    const float* p2 = pc2 + (size_t)b * 4 * NN2;
    const int base = s * SLICE;

    for (int m = threadIdx.x; m < SLICE; m += 128) {
        int g = base + m;
        float x = p2[g], y = p2[NN2 + g], z = p2[2 * NN2 + g];
        sh[m] = make_float4(x, y, z, x * x + y * y + z * z);
    }
    __syncthreads();

    const int n = blockIdx.x * 128 + threadIdx.x;
    const float* p1 = pc1 + (size_t)b * 4 * NN1;
    const float qx = p1[n], qy = p1[NN1 + n], qz = p1[2 * NN1 + n];

    float dminp = __int_as_float(0x7f800000);
    #pragma unroll 8
    for (int m = 0; m < SLICE; ++m) {
        float4 p = sh[m];
        float dot = fmaf(qx, p.x, fmaf(qy, p.y, qz * p.z));
        float dp  = fmaf(-2.0f, dot, p.w);
        dminp = fminf(dminp, dp);
    }
    g_partmin[(size_t)s * BB * NN1 + (size_t)b * NN1 + n] = dminp;
}

// ---------------------------------------------------------------------------
// Kernel B: per-slice softmax partial sums. Every block recombines the 4
// partial mins (same value everywhere -> deterministic), derives
// smax = 2/max(dmin,1e-5) and the d'-threshold CLAMPED to the global min
// (so the argmin element always passes in its slice -> total sumw >= 1).
// Groups of 8 elements share ONE branch (amortizes the divergence envelope).
// ---------------------------------------------------------------------------
__global__ void __launch_bounds__(128) nn_soft_kernel(const float* __restrict__ pc1,
                                                      const float* __restrict__ pc2)
{
    __shared__ float4 sh[SLICE];
    const int b = blockIdx.z;
    const int s = blockIdx.y;
    const float* p2 = pc2 + (size_t)b * 4 * NN2;
    const int base = s * SLICE;

    for (int m = threadIdx.x; m < SLICE; m += 128) {
        int g = base + m;
        float x = p2[g], y = p2[NN2 + g], z = p2[2 * NN2 + g];
        sh[m] = make_float4(x, y, z, x * x + y * y + z * z);
    }
    __syncthreads();

    const int n = blockIdx.x * 128 + threadIdx.x;
    const size_t qidx = (size_t)b * NN1 + n;
    const float* p1 = pc1 + (size_t)b * 4 * NN1;
    const float qx = p1[n], qy = p1[NN1 + n], qz = p1[2 * NN1 + n];
    const float q2 = qx * qx + qy * qy + qz * qz;

    const float INF = __int_as_float(0x7f800000);

    // global min of d' (deterministic merge of the 4 slice partials)
    float dminp = fminf(fminf(g_partmin[qidx],
                              g_partmin[(size_t)BB * NN1 + qidx]),
                        fminf(g_partmin[2 * (size_t)BB * NN1 + qidx],
                              g_partmin[3 * (size_t)BB * NN1 + qidx]));

    const float dmin = dminp + q2;
    const float smax = __fdividef(2.0f, fmaxf(dmin, 1e-5f));
    const float dthr_p = (smax > CUT)
                       ? fmaxf(__fdividef(2.0f, smax - CUT) - q2, dminp)
                       : INF;

    float sumw = 0.0f, a0 = 0.0f, a1 = 0.0f, a2 = 0.0f;

    for (int m0 = 0; m0 < SLICE; m0 += 8) {
        float dp[8];
        float gmin = INF;
        #pragma unroll
        for (int j = 0; j < 8; ++j) {
            float4 p = sh[m0 + j];
            float dot = fmaf(qx, p.x, fmaf(qy, p.y, qz * p.z));
            dp[j] = fmaf(-2.0f, dot, p.w);
            gmin = fminf(gmin, dp[j]);
        }
        if (gmin <= dthr_p) {
            #pragma unroll
            for (int j = 0; j < 8; ++j) {
                if (dp[j] <= dthr_p) {
                    float d = fmaxf(dp[j] + q2, 1e-5f);
                    float sc = __fdividef(2.0f, d);
                    float w = __expf(sc - smax);   // <= 1 by construction
                    float4 p = sh[m0 + j];
                    sumw += w;
                    a0 = fmaf(w, p.x, a0);
                    a1 = fmaf(w, p.y, a1);
                    a2 = fmaf(w, p.z, a2);
                }
            }
        }
    }

    const size_t sb = (size_t)s * 4 * BB * NN1;
    g_part[sb + 0 * (size_t)BB * NN1 + qidx] = sumw;
    g_part[sb + 1 * (size_t)BB * NN1 + qidx] = a0;
    g_part[sb + 2 * (size_t)BB * NN1 + qidx] = a1;
    g_part[sb + 3 * (size_t)BB * NN1 + qidx] = a2;
}

// ---------------------------------------------------------------------------
// Kernel C: merge the 4 slice partials -> pc_nearest + dist per query.
// ---------------------------------------------------------------------------
__global__ void __launch_bounds__(256) nn_merge_kernel(const float* __restrict__ pc1)
{
    const int idx = blockIdx.x * 256 + threadIdx.x;    // 0 .. BB*NN1-1
    const int b = idx / NN1;
    const int n = idx - b * NN1;

    float sumw = 0.0f, a0 = 0.0f, a1 = 0.0f, a2 = 0.0f;
    #pragma unroll
    for (int s = 0; s < NSLICE; ++s) {
        const size_t sb = (size_t)s * 4 * BB * NN1 + idx;
        sumw += g_part[sb];
        a0   += g_part[sb + 1 * (size_t)BB * NN1];
        a1   += g_part[sb + 2 * (size_t)BB * NN1];
        a2   += g_part[sb + 3 * (size_t)BB * NN1];
    }

    const float* p1 = pc1 + (size_t)b * 4 * NN1;
    const float qx = p1[n], qy = p1[NN1 + n], qz = p1[2 * NN1 + n];

    float inv = __fdividef(1.0f, sumw);                // sumw >= 1 (argmin)
    float nx = a0 * inv, ny = a1 * inv, nz = a2 * inv;
    float ddx = qx - nx, ddy = qy - ny, ddz = qz - nz;
    float dist = sqrtf(ddx * ddx + ddy * ddy + ddz * ddz);

    g_near[((size_t)b * 3 + 0) * NN1 + n] = nx;
    g_near[((size_t)b * 3 + 1) * NN1 + n] = ny;
    g_near[((size_t)b * 3 + 2) * NN1 + n] = nz;
    g_dist[idx] = dist;
}

// ---------------------------------------------------------------------------
// Kernel D: one block per batch. fp64 reductions (mean, masked sums, H),
// then thread 0 does the small dense tail (SVD/Kabsch/quat) in fp32 —
// the fp64 serial chain was ~100us; fp32 cuts it to ~5us, with error ~1e-6.
// Output layout: T[8*16] | q[8*4] | t[8*3]
// ---------------------------------------------------------------------------
__device__ inline float det3f(const float A[3][3])
{
    return A[0][0] * (A[1][1] * A[2][2] - A[1][2] * A[2][1])
         - A[0][1] * (A[1][0] * A[2][2] - A[1][2] * A[2][0])
         + A[0][2] * (A[1][0] * A[2][1] - A[1][1] * A[2][0]);
}

__global__ void __launch_bounds__(256) finalize_kernel(const float* __restrict__ pc1,
                                                       float* __restrict__ out)
{
    const int b = blockIdx.x;
    const int tid = threadIdx.x;
    const float* p1 = pc1 + (size_t)b * 4 * NN1;
    const float* nr = g_near + (size_t)b * 3 * NN1;
    const float* ds = g_dist + (size_t)b * NN1;

    __shared__ double warp_red[16][8];
    __shared__ double s_mean;

    // ---- phase 1: mean distance ----
    double lsum = 0.0;
    for (int i = tid; i < NN1; i += 256) lsum += (double)ds[i];
    for (int o = 16; o > 0; o >>= 1) lsum += __shfl_down_sync(0xffffffffu, lsum, o);
    if ((tid & 31) == 0) warp_red[0][tid >> 5] = lsum;
    __syncthreads();
    if (tid == 0) {
        double t = 0.0;
        for (int w = 0; w < 8; ++w) t += warp_red[0][w];
        s_mean = t / (double)NN1;
    }
    __syncthreads();
    const float mean = (float)s_mean;

    // ---- phase 2: masked sums (fp64 accumulation) ----
    double acc[16];
    #pragma unroll
    for (int k = 0; k < 16; ++k) acc[k] = 0.0;

    for (int i = tid; i < NN1; i += 256) {
        float d = ds[i];
        float z = (d - mean - 1e-5f) * -1e10f;     // REJECT_RATIO=1
        float ind = 1.0f / (1.0f + __expf(-z));    // exact 0/1 step in fp32
        if (ind > 0.0f) {
            double w = (double)ind;
            double x1 = p1[i], y1 = p1[NN1 + i], z1 = p1[2 * NN1 + i];
            double x2 = nr[i], y2 = nr[NN1 + i], z2 = nr[2 * NN1 + i];
            acc[0] += w;
            acc[1] += w * x1;  acc[2] += w * y1;  acc[3] += w * z1;
            acc[4] += w * x2;  acc[5] += w * y2;  acc[6] += w * z2;
            acc[7]  += w * x1 * x2;  acc[8]  += w * x1 * y2;  acc[9]  += w * x1 * z2;
            acc[10] += w * y1 * x2;  acc[11] += w * y1 * y2;  acc[12] += w * y1 * z2;
            acc[13] += w * z1 * x2;  acc[14] += w * z1 * y2;  acc[15] += w * z1 * z2;
        }
    }
    #pragma unroll
    for (int k = 0; k < 16; ++k) {
        double v = acc[k];
        for (int o = 16; o > 0; o >>= 1) v += __shfl_down_sync(0xffffffffu, v, o);
        if ((tid & 31) == 0) warp_red[k][tid >> 5] = v;
    }
    __syncthreads();
    if (tid != 0) return;

    double tot[16];
    for (int k = 0; k < 16; ++k) {
        double t = 0.0;
        for (int w = 0; w < 8; ++w) t += warp_red[k][w];
        tot[k] = t;
    }

    const double wsum = tot[0];
    // centroids and centered cross-covariance in fp64 (cancellation), then fp32
    float c1[3], c2[3], H[3][3];
    for (int i = 0; i < 3; ++i) {
        c1[i] = (float)(tot[1 + i] / wsum);
        c2[i] = (float)(tot[4 + i] / wsum);
    }
    for (int i = 0; i < 3; ++i)
        for (int j = 0; j < 3; ++j)
            H[i][j] = (float)(tot[7 + i * 3 + j] - tot[1 + i] * tot[4 + j] / wsum);

    // ---- fp32 SVD of H via Jacobi on S = H^T H ----
    float S[3][3], V[3][3];
    for (int i = 0; i < 3; ++i)
        for (int j = 0; j < 3; ++j) {
            float t = 0.0f;
            for (int k = 0; k < 3; ++k) t += H[k][i] * H[k][j];
            S[i][j] = t;
            V[i][j] = (i == j) ? 1.0f : 0.0f;
        }
    for (int sweep = 0; sweep < 8; ++sweep) {
        for (int pi = 0; pi < 3; ++pi) {
            const int p = (pi == 2) ? 1 : 0;
            const int q = (pi == 0) ? 1 : 2;
            float apq = S[p][q];
            if (fabsf(apq) < 1e-30f) continue;
            float theta = (S[q][q] - S[p][p]) / (2.0f * apq);
            float tt = copysignf(1.0f, theta) / (fabsf(theta) + sqrtf(theta * theta + 1.0f));
            float c = rsqrtf(tt * tt + 1.0f);
            float sn = tt * c;
            for (int k = 0; k < 3; ++k) { float a = S[k][p], bb = S[k][q]; S[k][p] = c * a - sn * bb; S[k][q] = sn * a + c * bb; }
            for (int k = 0; k < 3; ++k) { float a = S[p][k], bb = S[q][k]; S[p][k] = c * a - sn * bb; S[q][k] = sn * a + c * bb; }
            for (int k = 0; k < 3; ++k) { float a = V[k][p], bb = V[k][q]; V[k][p] = c * a - sn * bb; V[k][q] = sn * a + c * bb; }
        }
    }
    float lam[3] = { S[0][0], S[1][1], S[2][2] };
    for (int i = 0; i < 2; ++i)
        for (int j = i + 1; j < 3; ++j)
            if (lam[j] > lam[i]) {
                float t = lam[i]; lam[i] = lam[j]; lam[j] = t;
                for (int k = 0; k < 3; ++k) { float v = V[k][i]; V[k][i] = V[k][j]; V[k][j] = v; }
            }

    // U columns: u_i = H v_i, Gram-Schmidt orthonormalized (keeps det sign)
    float U[3][3];
    for (int i = 0; i < 3; ++i) {
        float u[3];
        for (int k = 0; k < 3; ++k) {
            float t = 0.0f;
            for (int j = 0; j < 3; ++j) t += H[k][j] * V[j][i];
            u[k] = t;
        }
        for (int pc = 0; pc < i; ++pc) {
            float dpp = u[0] * U[0][pc] + u[1] * U[1][pc] + u[2] * U[2][pc];
            for (int k = 0; k < 3; ++k) u[k] -= dpp * U[k][pc];
        }
        float nrm = sqrtf(u[0] * u[0] + u[1] * u[1] + u[2] * u[2]);
        float innr = 1.0f / fmaxf(nrm, 1e-30f);
        for (int k = 0; k < 3; ++k) U[k][i] = u[k] * innr;
    }

    float sign = (det3f(U) * det3f(V) < 0.0f) ? -1.0f : 1.0f;
    for (int k = 0; k < 3; ++k) V[k][2] *= sign;

    float R[3][3];
    for (int i = 0; i < 3; ++i)
        for (int j = 0; j < 3; ++j) {
            float t = 0.0f;
            for (int k = 0; k < 3; ++k) t += V[i][k] * U[j][k];
            R[i][j] = t;
        }
    float tv[3];
    for (int i = 0; i < 3; ++i)
        tv[i] = c2[i] - (R[i][0] * c1[0] + R[i][1] * c1[1] + R[i][2] * c1[2]);

    // ---- write outputs: T | q | t ----
    float* To = out + b * 16;
    for (int i = 0; i < 3; ++i) {
        for (int j = 0; j < 3; ++j) To[i * 4 + j] = R[i][j];
        To[i * 4 + 3] = tv[i];
    }
    To[12] = 0.0f; To[13] = 0.0f; To[14] = 0.0f; To[15] = 1.0f;

    float trp = R[0][0] + R[1][1] + R[2][2];
    float qw = 0.5f * sqrtf(fmaxf(1.0f + trp, 1e-12f));
    float qxv = 0.5f * sqrtf(fmaxf(1.0f + R[0][0] - R[1][1] - R[2][2], 1e-12f))
              * ((R[2][1] - R[1][2] >= 0.0f) ? 1.0f : -1.0f);
    float qyv = 0.5f * sqrtf(fmaxf(1.0f - R[0][0] + R[1][1] - R[2][2], 1e-12f))
              * ((R[0][2] - R[2][0] >= 0.0f) ? 1.0f : -1.0f);
    float qzv = 0.5f * sqrtf(fmaxf(1.0f - R[0][0] - R[1][1] + R[2][2], 1e-12f))
              * ((R[1][0] - R[0][1] >= 0.0f) ? 1.0f : -1.0f);

    float* qo = out + BB * 16 + b * 4;
    qo[0] = qw; qo[1] = qxv; qo[2] = qyv; qo[3] = qzv;

    float* to = out + BB * 16 + BB * 4 + b * 3;
    to[0] = tv[0]; to[1] = tv[1]; to[2] = tv[2];
}

// ---------------------------------------------------------------------------
extern "C" void kernel_launch(void* const* d_in, const int* in_sizes, int n_in,
                              void* d_out, int out_size)
{
    const float* pc1 = (const float*)d_in[0];
    const float* pc2 = (const float*)d_in[1];
    float* out = (float*)d_out;

    dim3 grid_nn(NN1 / 128, NSLICE, BB);
    nn_min_kernel  <<<grid_nn, 128>>>(pc1, pc2);
    nn_soft_kernel <<<grid_nn, 128>>>(pc1, pc2);
    nn_merge_kernel<<<(BB * NN1) / 256, 256>>>(pc1);
    finalize_kernel<<<BB, 256>>>(pc1, out);
}

// round 14
// speedup vs baseline: 4.3484x; 1.0102x over previous
#include <cuda_runtime.h>
#include <math.h>

#define BB      8
#define NN1     4096
#define NN2     4096
#define NSLICE  4
#define SLICE   (NN2 / NSLICE)      // 1024 pc2 points per slice (16KB float4)
#define CUT     30.0f               // exp(s-smax) < e^-30 -> negligible, dropped

// Scratch (device globals — no runtime allocation allowed)
__device__ float g_partmin[NSLICE * BB * NN1];     // per-slice min of d'
__device__ float g_part[NSLICE * 4 * BB * NN1];    // per-slice {sumw,a0,a1,a2}
__device__ float g_near[BB * 3 * NN1];
__device__ float g_dist[BB * NN1];
__device__ float g_smax[BB * NN1];
__device__ float g_dthr[BB * NN1];                 // d'-threshold (sparse only)
__device__ int   g_list_sparse[BB][NN1];
__device__ int   g_list_dense[BB][NN1];
__device__ int   g_cnt_sparse[BB];
__device__ int   g_cnt_dense[BB];

// ---------------------------------------------------------------------------
// Kernel 0: reset the per-batch list counters (graph is replayed -> must
// re-zero every launch).
// ---------------------------------------------------------------------------
__global__ void reset_kernel()
{
    if (threadIdx.x < BB) {
        g_cnt_sparse[threadIdx.x] = 0;
        g_cnt_dense[threadIdx.x] = 0;
    }
}

// ---------------------------------------------------------------------------
// Kernel A: branchless per-slice min of d' = |p2|^2 - 2 q.p2  (q^2 folded out)
// grid = (NN1/128, NSLICE, BB), 128 threads, 16KB smem.
// ---------------------------------------------------------------------------
__global__ void __launch_bounds__(128) nn_min_kernel(const float* __restrict__ pc1,
                                                     const float* __restrict__ pc2)
{
    __shared__ float4 sh[SLICE];
    const int b = blockIdx.z;
    const int s = blockIdx.y;
    const float* p2 = pc2 + (size_t)b * 4 * NN2;
    const int base = s * SLICE;

    for (int m = threadIdx.x; m < SLICE; m += 128) {
        int g = base + m;
        float x = p2[g], y = p2[NN2 + g], z = p2[2 * NN2 + g];
        sh[m] = make_float4(x, y, z, x * x + y * y + z * z);
    }
    __syncthreads();

    const int n = blockIdx.x * 128 + threadIdx.x;
    const float* p1 = pc1 + (size_t)b * 4 * NN1;
    const float qx = p1[n], qy = p1[NN1 + n], qz = p1[2 * NN1 + n];

    float dminp = __int_as_float(0x7f800000);
    #pragma unroll 8
    for (int m = 0; m < SLICE; ++m) {
        float4 p = sh[m];
        float dot = fmaf(qx, p.x, fmaf(qy, p.y, qz * p.z));
        float dp  = fmaf(-2.0f, dot, p.w);
        dminp = fminf(dminp, dp);
    }
    g_partmin[(size_t)s * BB * NN1 + (size_t)b * NN1 + n] = dminp;
}

// ---------------------------------------------------------------------------
// Kernel A2: merge the 4 slice mins, derive smax + clamped threshold, and
// partition queries into per-batch sparse/dense lists. List order is
// atomic-race-dependent but per-query results are order-independent ->
// outputs stay deterministic.
// ---------------------------------------------------------------------------
__global__ void __launch_bounds__(256) classify_kernel(const float* __restrict__ pc1)
{
    const int idx = blockIdx.x * 256 + threadIdx.x;    // 0 .. BB*NN1-1
    const int b = idx / NN1;
    const int n = idx - b * NN1;

    float dminp = fminf(fminf(g_partmin[idx],
                              g_partmin[(size_t)BB * NN1 + idx]),
                        fminf(g_partmin[2 * (size_t)BB * NN1 + idx],
                              g_partmin[3 * (size_t)BB * NN1 + idx]));

    const float* p1 = pc1 + (size_t)b * 4 * NN1;
    const float qx = p1[n], qy = p1[NN1 + n], qz = p1[2 * NN1 + n];
    const float q2 = qx * qx + qy * qy + qz * qz;

    const float dmin = dminp + q2;
    const float smax = __fdividef(2.0f, fmaxf(dmin, 1e-5f));
    const bool sparse = (smax > CUT);
    // CLAMP to dminp so the argmin element always passes (sumw >= 1, no NaN)
    const float dthr = sparse
                     ? fmaxf(__fdividef(2.0f, smax - CUT) - q2, dminp)
                     : __int_as_float(0x7f800000);

    g_smax[idx] = smax;
    g_dthr[idx] = dthr;

    if (sparse) {
        int p = atomicAdd(&g_cnt_sparse[b], 1);
        g_list_sparse[b][p] = n;
    } else {
        int p = atomicAdd(&g_cnt_dense[b], 1);
        g_list_dense[b][p] = n;
    }
}

// ---------------------------------------------------------------------------
// Kernel B1: SPARSE queries only (clean warps -> heavy path triggers only on
// genuine candidate groups, ~half the groups instead of all of them).
// Groups of 8 share one branch; fixed smax, no online rescale.
// ---------------------------------------------------------------------------
__global__ void __launch_bounds__(128) nn_sparse_kernel(const float* __restrict__ pc1,
                                                        const float* __restrict__ pc2)
{
    const int b = blockIdx.z;
    const int s = blockIdx.y;
    const int cnt = g_cnt_sparse[b];
    if (blockIdx.x * 128 >= cnt) return;               // uniform whole-block exit

    __shared__ float4 sh[SLICE];
    const float* p2 = pc2 + (size_t)b * 4 * NN2;
    const int base = s * SLICE;
    for (int m = threadIdx.x; m < SLICE; m += 128) {
        int g = base + m;
        float x = p2[g], y = p2[NN2 + g], z = p2[2 * NN2 + g];
        sh[m] = make_float4(x, y, z, x * x + y * y + z * z);
    }
    __syncthreads();

    const int i = blockIdx.x * 128 + threadIdx.x;
    const bool active = (i < cnt);
    const int n = active ? g_list_sparse[b][i] : 0;
    const size_t qidx = (size_t)b * NN1 + n;
    const float* p1 = pc1 + (size_t)b * 4 * NN1;
    const float qx = p1[n], qy = p1[NN1 + n], qz = p1[2 * NN1 + n];
    const float q2 = qx * qx + qy * qy + qz * qz;

    const float INF = __int_as_float(0x7f800000);
    const float smax = g_smax[qidx];
    const float dthr_p = active ? g_dthr[qidx] : -INF;  // inactive: never passes

    float sumw = 0.0f, a0 = 0.0f, a1 = 0.0f, a2 = 0.0f;

    for (int m0 = 0; m0 < SLICE; m0 += 8) {
        float dp[8];
        float gmin = INF;
        #pragma unroll
        for (int j = 0; j < 8; ++j) {
            float4 p = sh[m0 + j];
            float dot = fmaf(qx, p.x, fmaf(qy, p.y, qz * p.z));
            dp[j] = fmaf(-2.0f, dot, p.w);
            gmin = fminf(gmin, dp[j]);
        }
        if (gmin <= dthr_p) {
            #pragma unroll
            for (int j = 0; j < 8; ++j) {
                if (dp[j] <= dthr_p) {
                    float d = fmaxf(dp[j] + q2, 1e-5f);
                    float sc = __fdividef(2.0f, d);
                    float w = __expf(sc - smax);       // <= 1 by construction
                    float4 p = sh[m0 + j];
                    sumw += w;
                    a0 = fmaf(w, p.x, a0);
                    a1 = fmaf(w, p.y, a1);
                    a2 = fmaf(w, p.z, a2);
                }
            }
        }
    }

    if (active) {
        const size_t sb = (size_t)s * 4 * BB * NN1;
        g_part[sb + 0 * (size_t)BB * NN1 + qidx] = sumw;
        g_part[sb + 1 * (size_t)BB * NN1 + qidx] = a0;
        g_part[sb + 2 * (size_t)BB * NN1 + qidx] = a1;
        g_part[sb + 3 * (size_t)BB * NN1 + qidx] = a2;
    }
}

// ---------------------------------------------------------------------------
// Kernel B2: DENSE queries (no finite threshold): branchless full softmax.
// Few queries (~5%), sliced over m for parallelism; MUFU-paced but tiny.
// ---------------------------------------------------------------------------
__global__ void __launch_bounds__(128) nn_dense_kernel(const float* __restrict__ pc1,
                                                       const float* __restrict__ pc2)
{
    const int b = blockIdx.z;
    const int s = blockIdx.y;
    const int cnt = g_cnt_dense[b];
    if (blockIdx.x * 128 >= cnt) return;

    __shared__ float4 sh[SLICE];
    const float* p2 = pc2 + (size_t)b * 4 * NN2;
    const int base = s * SLICE;
    for (int m = threadIdx.x; m < SLICE; m += 128) {
        int g = base + m;
        float x = p2[g], y = p2[NN2 + g], z = p2[2 * NN2 + g];
        sh[m] = make_float4(x, y, z, x * x + y * y + z * z);
    }
    __syncthreads();

    const int i = blockIdx.x * 128 + threadIdx.x;
    const bool active = (i < cnt);
    const int n = active ? g_list_dense[b][i] : 0;
    const size_t qidx = (size_t)b * NN1 + n;
    const float* p1 = pc1 + (size_t)b * 4 * NN1;
    const float qx = p1[n], qy = p1[NN1 + n], qz = p1[2 * NN1 + n];
    const float q2 = qx * qx + qy * qy + qz * qz;
    const float smax = g_smax[qidx];

    float sumw = 0.0f, a0 = 0.0f, a1 = 0.0f, a2 = 0.0f;

    #pragma unroll 4
    for (int m = 0; m < SLICE; ++m) {
        float4 p = sh[m];
        float dot = fmaf(qx, p.x, fmaf(qy, p.y, qz * p.z));
        float dp  = fmaf(-2.0f, dot, p.w);
        float d = fmaxf(dp + q2, 1e-5f);
        float sc = __fdividef(2.0f, d);
        float w = __expf(sc - smax);
        sumw += w;
        a0 = fmaf(w, p.x, a0);
        a1 = fmaf(w, p.y, a1);
        a2 = fmaf(w, p.z, a2);
    }

    if (active) {
        const size_t sb = (size_t)s * 4 * BB * NN1;
        g_part[sb + 0 * (size_t)BB * NN1 + qidx] = sumw;
        g_part[sb + 1 * (size_t)BB * NN1 + qidx] = a0;
        g_part[sb + 2 * (size_t)BB * NN1 + qidx] = a1;
        g_part[sb + 3 * (size_t)BB * NN1 + qidx] = a2;
    }
}

// ---------------------------------------------------------------------------
// Kernel D: one block per batch. Phase 0 merges the 4 slice partials into
// pc_nearest/dist (and starts the mean sum). All accumulation in fp32
// (the fp64 DFMA chain was the 66us bottleneck; fp32 error ~1e-5 << 1e-3).
// Thread 0 then does the dense tail (SVD/Kabsch/quat) in fp32.
// Output layout: T[8*16] | q[8*4] | t[8*3]
// ---------------------------------------------------------------------------
__device__ inline float det3f(const float A[3][3])
{
    return A[0][0] * (A[1][1] * A[2][2] - A[1][2] * A[2][1])
         - A[0][1] * (A[1][0] * A[2][2] - A[1][2] * A[2][0])
         + A[0][2] * (A[1][0] * A[2][1] - A[1][1] * A[2][0]);
}

__global__ void __launch_bounds__(256) finalize_kernel(const float* __restrict__ pc1,
                                                       float* __restrict__ out)
{
    const int b = blockIdx.x;
    const int tid = threadIdx.x;
    const float* p1 = pc1 + (size_t)b * 4 * NN1;
    float* nr = g_near + (size_t)b * 3 * NN1;
    float* ds = g_dist + (size_t)b * NN1;

    __shared__ float warp_red[16][8];
    __shared__ float s_mean;

    // ---- phase 0: merge slice partials -> near/dist, accumulate mean ----
    float lsum = 0.0f;
    for (int i = tid; i < NN1; i += 256) {
        const size_t qidx = (size_t)b * NN1 + i;
        float sumw = 0.0f, a0 = 0.0f, a1 = 0.0f, a2 = 0.0f;
        #pragma unroll
        for (int s = 0; s < NSLICE; ++s) {
            const size_t sb = (size_t)s * 4 * BB * NN1 + qidx;
            sumw += g_part[sb];
            a0   += g_part[sb + 1 * (size_t)BB * NN1];
            a1   += g_part[sb + 2 * (size_t)BB * NN1];
            a2   += g_part[sb + 3 * (size_t)BB * NN1];
        }
        const float qx = p1[i], qy = p1[NN1 + i], qz = p1[2 * NN1 + i];
        float inv = __fdividef(1.0f, sumw);            // sumw >= 1 (argmin)
        float nx = a0 * inv, ny = a1 * inv, nz = a2 * inv;
        float ddx = qx - nx, ddy = qy - ny, ddz = qz - nz;
        float dist = sqrtf(ddx * ddx + ddy * ddy + ddz * ddz);
        nr[i] = nx; nr[NN1 + i] = ny; nr[2 * NN1 + i] = nz;
        ds[i] = dist;
        lsum += dist;
    }
    for (int o = 16; o > 0; o >>= 1) lsum += __shfl_down_sync(0xffffffffu, lsum, o);
    if ((tid & 31) == 0) warp_red[0][tid >> 5] = lsum;
    __syncthreads();
    if (tid == 0) {
        float t = 0.0f;
        for (int w = 0; w < 8; ++w) t += warp_red[0][w];
        s_mean = t / (float)NN1;
    }
    __syncthreads();
    const float mean = s_mean;

    // ---- phase 2: masked sums (fp32) ----
    float acc[16];
    #pragma unroll
    for (int k = 0; k < 16; ++k) acc[k] = 0.0f;

    for (int i = tid; i < NN1; i += 256) {
        float d = ds[i];
        float z = (d - mean - 1e-5f) * -1e10f;         // REJECT_RATIO=1
        float ind = 1.0f / (1.0f + __expf(-z));        // exact 0/1 step in fp32
        if (ind > 0.0f) {
            float w = ind;
            float x1 = p1[i], y1 = p1[NN1 + i], z1 = p1[2 * NN1 + i];
            float x2 = nr[i], y2 = nr[NN1 + i], z2 = nr[2 * NN1 + i];
            acc[0] += w;
            acc[1] += w * x1;  acc[2] += w * y1;  acc[3] += w * z1;
            acc[4] += w * x2;  acc[5] += w * y2;  acc[6] += w * z2;
            acc[7]  += w * x1 * x2;  acc[8]  += w * x1 * y2;  acc[9]  += w * x1 * z2;
            acc[10] += w * y1 * x2;  acc[11] += w * y1 * y2;  acc[12] += w * y1 * z2;
            acc[13] += w * z1 * x2;  acc[14] += w * z1 * y2;  acc[15] += w * z1 * z2;
        }
    }
    #pragma unroll
    for (int k = 0; k < 16; ++k) {
        float v = acc[k];
        for (int o = 16; o > 0; o >>= 1) v += __shfl_down_sync(0xffffffffu, v, o);
        if ((tid & 31) == 0) warp_red[k][tid >> 5] = v;
    }
    __syncthreads();
    if (tid != 0) return;

    float tot[16];
    for (int k = 0; k < 16; ++k) {
        float t = 0.0f;
        for (int w = 0; w < 8; ++w) t += warp_red[k][w];
        tot[k] = t;
    }

    const float wsum = tot[0];
    const float winv = 1.0f / wsum;
    float c1[3], c2[3], H[3][3];
    for (int i = 0; i < 3; ++i) {
        c1[i] = tot[1 + i] * winv;
        c2[i] = tot[4 + i] * winv;
    }
    for (int i = 0; i < 3; ++i)
        for (int j = 0; j < 3; ++j)
            H[i][j] = tot[7 + i * 3 + j] - tot[1 + i] * tot[4 + j] * winv;

    // ---- fp32 SVD of H via Jacobi on S = H^T H ----
    float S[3][3], V[3][3];
    for (int i = 0; i < 3; ++i)
        for (int j = 0; j < 3; ++j) {
            float t = 0.0f;
            for (int k = 0; k < 3; ++k) t += H[k][i] * H[k][j];
            S[i][j] = t;
            V[i][j] = (i == j) ? 1.0f : 0.0f;
        }
    for (int sweep = 0; sweep < 8; ++sweep) {
        for (int pi = 0; pi < 3; ++pi) {
            const int p = (pi == 2) ? 1 : 0;
            const int q = (pi == 0) ? 1 : 2;
            float apq = S[p][q];
            if (fabsf(apq) < 1e-30f) continue;
            float theta = (S[q][q] - S[p][p]) / (2.0f * apq);
            float tt = copysignf(1.0f, theta) / (fabsf(theta) + sqrtf(theta * theta + 1.0f));
            float c = rsqrtf(tt * tt + 1.0f);
            float sn = tt * c;
            for (int k = 0; k < 3; ++k) { float a = S[k][p], bb = S[k][q]; S[k][p] = c * a - sn * bb; S[k][q] = sn * a + c * bb; }
            for (int k = 0; k < 3; ++k) { float a = S[p][k], bb = S[q][k]; S[p][k] = c * a - sn * bb; S[q][k] = sn * a + c * bb; }
            for (int k = 0; k < 3; ++k) { float a = V[k][p], bb = V[k][q]; V[k][p] = c * a - sn * bb; V[k][q] = sn * a + c * bb; }
        }
    }
    float lam[3] = { S[0][0], S[1][1], S[2][2] };
    for (int i = 0; i < 2; ++i)
        for (int j = i + 1; j < 3; ++j)
            if (lam[j] > lam[i]) {
                float t = lam[i]; lam[i] = lam[j]; lam[j] = t;
                for (int k = 0; k < 3; ++k) { float v = V[k][i]; V[k][i] = V[k][j]; V[k][j] = v; }
            }

    // U columns: u_i = H v_i, Gram-Schmidt orthonormalized (keeps det sign)
    float U[3][3];
    for (int i = 0; i < 3; ++i) {
        float u[3];
        for (int k = 0; k < 3; ++k) {
            float t = 0.0f;
            for (int j = 0; j < 3; ++j) t += H[k][j] * V[j][i];
            u[k] = t;
        }
        for (int pc = 0; pc < i; ++pc) {
            float dpp = u[0] * U[0][pc] + u[1] * U[1][pc] + u[2] * U[2][pc];
            for (int k = 0; k < 3; ++k) u[k] -= dpp * U[k][pc];
        }
        float nrm = sqrtf(u[0] * u[0] + u[1] * u[1] + u[2] * u[2]);
        float innr = 1.0f / fmaxf(nrm, 1e-30f);
        for (int k = 0; k < 3; ++k) U[k][i] = u[k] * innr;
    }

    float sign = (det3f(U) * det3f(V) < 0.0f) ? -1.0f : 1.0f;
    for (int k = 0; k < 3; ++k) V[k][2] *= sign;

    float R[3][3];
    for (int i = 0; i < 3; ++i)
        for (int j = 0; j < 3; ++j) {
            float t = 0.0f;
            for (int k = 0; k < 3; ++k) t += V[i][k] * U[j][k];
            R[i][j] = t;
        }
    float tv[3];
    for (int i = 0; i < 3; ++i)
        tv[i] = c2[i] - (R[i][0] * c1[0] + R[i][1] * c1[1] + R[i][2] * c1[2]);

    // ---- write outputs: T | q | t ----
    float* To = out + b * 16;
    for (int i = 0; i < 3; ++i) {
        for (int j = 0; j < 3; ++j) To[i * 4 + j] = R[i][j];
        To[i * 4 + 3] = tv[i];
    }
    To[12] = 0.0f; To[13] = 0.0f; To[14] = 0.0f; To[15] = 1.0f;

    float trp = R[0][0] + R[1][1] + R[2][2];
    float qw = 0.5f * sqrtf(fmaxf(1.0f + trp, 1e-12f));
    float qxv = 0.5f * sqrtf(fmaxf(1.0f + R[0][0] - R[1][1] - R[2][2], 1e-12f))
              * ((R[2][1] - R[1][2] >= 0.0f) ? 1.0f : -1.0f);
    float qyv = 0.5f * sqrtf(fmaxf(1.0f - R[0][0] + R[1][1] - R[2][2], 1e-12f))
              * ((R[0][2] - R[2][0] >= 0.0f) ? 1.0f : -1.0f);
    float qzv = 0.5f * sqrtf(fmaxf(1.0f - R[0][0] - R[1][1] + R[2][2], 1e-12f))
              * ((R[1][0] - R[0][1] >= 0.0f) ? 1.0f : -1.0f);

    float* qo = out + BB * 16 + b * 4;
    qo[0] = qw; qo[1] = qxv; qo[2] = qyv; qo[3] = qzv;

    float* to = out + BB * 16 + BB * 4 + b * 3;
    to[0] = tv[0]; to[1] = tv[1]; to[2] = tv[2];
}

// ---------------------------------------------------------------------------
extern "C" void kernel_launch(void* const* d_in, const int* in_sizes, int n_in,
                              void* d_out, int out_size)
{
    const float* pc1 = (const float*)d_in[0];
    const float* pc2 = (const float*)d_in[1];
    float* out = (float*)d_out;

    dim3 grid_nn(NN1 / 128, NSLICE, BB);
    reset_kernel   <<<1, 32>>>();
    nn_min_kernel  <<<grid_nn, 128>>>(pc1, pc2);
    classify_kernel<<<(BB * NN1) / 256, 256>>>(pc1);
    nn_sparse_kernel<<<grid_nn, 128>>>(pc1, pc2);
    nn_dense_kernel <<<grid_nn, 128>>>(pc1, pc2);
    finalize_kernel<<<BB, 256>>>(pc1, out);
}